// round 17
// baseline (speedup 1.0000x reference)
#include <cuda_runtime.h>
#include <cuda_bf16.h>
#include <math.h>
#include <stdint.h>

#define HH 768
#define LAYERS 10
#define WW 10
#define BB 512
#define G4H 3072
#define TB 5120          // WW*BB
#define KFC1 (WW*HH)     // 7680

#define KT 32            // K-slab in elements
#define STRIDE 20        // u32 per smem row (16 used + 4 pad; ldmatrix conflict-free)
#define PLANE (128 * STRIDE)               // u32 per 128-row plane
#define SMEM_BYTES (2 * 4 * PLANE * 4)     // 81920 (128x128, 2-stage)

#define LGRID 296        // 148 SMs x occ 2 — all co-resident
#define NBATCH 400       // LSTM batches: l*40 + t*4 + chain
#define TPB 24           // tiles per LSTM batch (128x128)
#define NFC0 240         // fc0 tiles (40 sextets)
#define NFC1 240         // fc1 tiles (40 pseudo-batches x 6)
#define NTICK (NFC0 + NBATCH * TPB + NFC1)   // 10080

typedef __nv_bfloat16 bf16;

// ---------------- scratch (device globals; allocation-free rule) -------------
__device__ bf16  g_xhi[11 * TB * HH], g_xlo[11 * TB * HH];   // x[l][t][b][h], l=0..10
__device__ float g_c[LAYERS * BB * HH];                      // per-layer cell state
__device__ bf16  g_xcathi[TB * HH], g_xcatlo[TB * HH];       // fc0 input (W,B,H) split
__device__ bf16  g_fc0whi[HH * HH],   g_fc0wlo[HH * HH];
__device__ bf16  g_fc1whi[HH * KFC1], g_fc1wlo[HH * KFC1];
__device__ bf16  g_wihhi[LAYERS * G4H * HH], g_wihlo[LAYERS * G4H * HH];
__device__ bf16  g_whhhi[LAYERS * G4H * HH], g_whhlo[LAYERS * G4H * HH];
__device__ float g_bcomb[LAYERS * G4H];
__device__ float g_part[WW * BB * HH];                       // fc1 partials by t
// sched: [0..439] done (400 LSTM + 40 fc0), [440..839] dep, [840..1239] readyq,
//        [1240] ticket, [1241] qtail, [1242..1281] fc1 ready flags
__device__ int   g_sched[1344];

// ---------------- helpers ----------------------------------------------------
__device__ __forceinline__ void split1(float v, bf16& h, bf16& l)
{
    h = __float2bfloat16_rn(v);
    l = __float2bfloat16_rn(v - __bfloat162float(h));
}

__device__ __forceinline__ float sigm(float x) { return 1.0f / (1.0f + expf(-x)); }

__device__ __forceinline__ void cpasync16(void* dst, const void* src)
{
    uint32_t s = (uint32_t)__cvta_generic_to_shared(dst);
    asm volatile("cp.async.cg.shared.global [%0], [%1], 16;\n" :: "r"(s), "l"(src));
}
__device__ __forceinline__ void cp_commit() { asm volatile("cp.async.commit_group;\n"); }

__device__ __forceinline__ void mma_bf16(float* c, const uint32_t* a, const uint32_t* b)
{
    asm volatile(
        "mma.sync.aligned.m16n8k16.row.col.f32.bf16.bf16.f32 "
        "{%0,%1,%2,%3}, {%4,%5,%6,%7}, {%8,%9}, {%0,%1,%2,%3};"
        : "+f"(c[0]), "+f"(c[1]), "+f"(c[2]), "+f"(c[3])
        : "r"(a[0]), "r"(a[1]), "r"(a[2]), "r"(a[3]), "r"(b[0]), "r"(b[1]));
}

__device__ __forceinline__ void ldsm4(uint32_t* r, uint32_t saddr)
{
    asm volatile("ldmatrix.sync.aligned.m8n8.x4.shared.b16 {%0,%1,%2,%3}, [%4];"
                 : "=r"(r[0]), "=r"(r[1]), "=r"(r[2]), "=r"(r[3]) : "r"(saddr));
}

// one k16, RAW-free ordering: hh sweep, hl sweep, lh sweep (bit-identical per-acc order)
#define K16_COMPUTE(Ahb, Alb, aoff, kb, bh, bl, acc) \
    _Pragma("unroll") \
    for (int mi = 0; mi < 4; mi++) { \
        uint32_t ao = (aoff) + (kb) + (uint32_t)(mi * 16 * STRIDE) * 4; \
        uint32_t ah[4], al[4]; \
        ldsm4(ah, (Ahb) + ao); \
        ldsm4(al, (Alb) + ao); \
        _Pragma("unroll") \
        for (int ni = 0; ni < 4; ni++) mma_bf16(acc[mi][ni], ah, bh[ni]); \
        _Pragma("unroll") \
        for (int ni = 0; ni < 4; ni++) mma_bf16(acc[mi][ni], ah, bl[ni]); \
        _Pragma("unroll") \
        for (int ni = 0; ni < 4; ni++) mma_bf16(acc[mi][ni], al, bh[ni]); \
    }

// ---- dataflow-scheduled mega kernel: fc0 + 10x10 LSTM + fc1 partials --------
// ticket < 240:        fc0 tile (dep-free), split-store x[0]
// ticket < 9840:       LSTM tile via slot queue (fused K=1536 GEMM + cell)
// else:                fc1 partial tile (ready flag per (t,ch)), fp32 -> part[t]
__global__ __launch_bounds__(256, 2) void mega_kernel(
    bf16* __restrict__ xhi, bf16* __restrict__ xlo,
    const bf16* __restrict__ xcathi, const bf16* __restrict__ xcatlo,
    const bf16* __restrict__ fc0whi, const bf16* __restrict__ fc0wlo,
    const float* __restrict__ fc0b,
    const bf16* __restrict__ fc1whi, const bf16* __restrict__ fc1wlo,
    const bf16* __restrict__ wihhi, const bf16* __restrict__ wihlo,
    const bf16* __restrict__ whhhi, const bf16* __restrict__ whhlo,
    const float* __restrict__ bcomb, float* __restrict__ call,
    float* __restrict__ part,
    int* __restrict__ sched)
{
    extern __shared__ uint32_t sm[];
    __shared__ int s_ticket, s_batch;
    const int tid = threadIdx.x;
    const int lane = tid & 31;
    const int wid = tid >> 5;
    const int wm = wid >> 2;
    const int wn = wid & 3;
    const int q = lane >> 2;
    const int r = lane & 3;

    const int lrowA = ((lane >> 3) & 1) * 8 + (lane & 7);
    const int lchA  = (lane >> 4) & 1;
    const int lrowB = ((lane >> 4) & 1) * 8 + (lane & 7);
    const int lchB  = (lane >> 3) & 1;
    const uint32_t smem_b = (uint32_t)__cvta_generic_to_shared(sm);

    int* done   = sched;          // [0..439]
    int* dep    = sched + 440;    // [0..399]
    int* rq     = sched + 840;    // [0..399]
    int* fc1rdy = sched + 1242;   // [0..39]

    for (;;) {
        if (tid == 0) s_ticket = atomicAdd(&sched[1240], 1);
        __syncthreads();
        int ticket = s_ticket;
        if (ticket >= NTICK) break;

        // ---- decode work item ----
        // kind: 0 = fc0, 1 = LSTM, 2 = fc1 partial
        int kind;
        int bm, bn, t, l, ch, NSLAB, fcb;
        const bf16 *A1h, *A1l, *A2h, *A2l, *B1h, *B1l, *B2h, *B2l;
        if (ticket < NFC0) {
            kind = 0;
            fcb = ticket / 6;               // sextet 0..39  (t*4+ch)
            int cn = ticket % 6;
            t = fcb >> 2; ch = fcb & 3; l = 0;
            bm = t * BB + ch * 128;
            bn = cn * 128;
            NSLAB = 24;
            A1h = xcathi; A1l = xcatlo;
            B1h = fc0whi; B1l = fc0wlo;
            A2h = A1h; A2l = A1l; B2h = B1h; B2l = B1l;
        } else if (ticket < NFC0 + NBATCH * TPB) {
            kind = 1;
            int tk = ticket - NFC0;
            int slot = tk / TPB;
            bn = (tk % TPB) * 128;
            if (tid == 0) {
                int b;
                while ((b = __ldcg(&rq[slot])) < 0) __nanosleep(100);
                s_batch = b;
            }
            __syncthreads();
            int batch = s_batch;
            ch = batch & 3;
            t  = (batch >> 2) % 10;
            l  = batch / 40;
            bm = ch * 128;
            fcb = batch;
            A1h = xhi + ((size_t)l * WW + t) * BB * HH;
            A1l = xlo + ((size_t)l * WW + t) * BB * HH;
            A2h = xhi + ((size_t)(l + 1) * WW + (t - 1)) * BB * HH;
            A2l = xlo + ((size_t)(l + 1) * WW + (t - 1)) * BB * HH;
            B1h = wihhi + (size_t)l * G4H * HH;
            B1l = wihlo + (size_t)l * G4H * HH;
            B2h = whhhi + (size_t)l * G4H * HH;
            B2l = whhlo + (size_t)l * G4H * HH;
            NSLAB = t ? 48 : 24;
        } else {
            kind = 2;
            int tk = ticket - NFC0 - NBATCH * TPB;
            fcb = tk / 6;                   // pseudo-batch 0..39 (t*4+ch)
            int cn = tk % 6;
            t = fcb >> 2; ch = fcb & 3; l = 0;
            bm = ch * 128;
            bn = cn * 128;
            NSLAB = 24;
            if (tid == 0) {
                while (__ldcg(&fc1rdy[fcb]) == 0) __nanosleep(100);
            }
            __syncthreads();
            // A = x[10][t] rows b, cols kk; B = fc1_w rows n, col t*HH+kk
            A1h = xhi + ((size_t)(10 * WW) + t) * BB * HH;
            A1l = xlo + ((size_t)(10 * WW) + t) * BB * HH;
            B1h = fc1whi + (size_t)t * HH;   // row stride KFC1 handled in loader
            B1l = fc1wlo + (size_t)t * HH;
            A2h = A1h; A2l = A1l; B2h = B1h; B2l = B1l;
        }

        float acc[4][4][4];
#pragma unroll
        for (int i = 0; i < 4; i++)
#pragma unroll
            for (int j = 0; j < 4; j++)
#pragma unroll
                for (int v = 0; v < 4; v++) acc[i][j][v] = 0.f;

        const size_t bstride = (kind == 2) ? (size_t)KFC1 : (size_t)HH;

        auto issue = [&](int slab, int stage) {
            int seg2 = slab >= 24;
            int k0 = (seg2 ? slab - 24 : slab) * KT;
            const bf16* Ah = seg2 ? A2h : A1h;
            const bf16* Al = seg2 ? A2l : A1l;
            const bf16* Bh = seg2 ? B2h : B1h;
            const bf16* Bl = seg2 ? B2l : B1l;
            uint32_t* base = sm + stage * 4 * PLANE;
#pragma unroll
            for (int i = 0; i < 2; i++) {
                int f = tid + i * 256;
                int m = f >> 2, cc = f & 3;
                size_t ga = (size_t)(bm + m) * HH + k0 + cc * 8;
                size_t gb = (size_t)(bn + m) * bstride + k0 + cc * 8;
                int off = m * STRIDE + cc * 4;
                cpasync16(base + 0 * PLANE + off, Ah + ga);
                cpasync16(base + 1 * PLANE + off, Al + ga);
                cpasync16(base + 2 * PLANE + off, Bh + gb);
                cpasync16(base + 3 * PLANE + off, Bl + gb);
            }
            cp_commit();
        };

        auto compute = [&](int stage) {
            uint32_t Ahb = smem_b + (stage * 4 + 0) * PLANE * 4;
            uint32_t Alb = smem_b + (stage * 4 + 1) * PLANE * 4;
            uint32_t Bhb = smem_b + (stage * 4 + 2) * PLANE * 4;
            uint32_t Blb = smem_b + (stage * 4 + 3) * PLANE * 4;
            uint32_t aoff = (uint32_t)((wm * 64 + lrowA) * STRIDE + lchA * 4) * 4;
            uint32_t boff = (uint32_t)((wn * 32 + lrowB) * STRIDE + lchB * 4) * 4;
#pragma unroll
            for (int k16 = 0; k16 < 2; k16++) {
                uint32_t kb = (uint32_t)(k16 * 8) * 4;
                uint32_t bh[4][2], bl[4][2];
#pragma unroll
                for (int p = 0; p < 2; p++) {
                    uint32_t bo = boff + kb + (uint32_t)(p * 16 * STRIDE) * 4;
                    uint32_t r4[4];
                    ldsm4(r4, Bhb + bo);
                    bh[p * 2][0] = r4[0]; bh[p * 2][1] = r4[1];
                    bh[p * 2 + 1][0] = r4[2]; bh[p * 2 + 1][1] = r4[3];
                    ldsm4(r4, Blb + bo);
                    bl[p * 2][0] = r4[0]; bl[p * 2][1] = r4[1];
                    bl[p * 2 + 1][0] = r4[2]; bl[p * 2 + 1][1] = r4[3];
                }
                K16_COMPUTE(Ahb, Alb, aoff, kb, bh, bl, acc)
            }
        };

        issue(0, 0);
        issue(1, 1);
        for (int s = 0; s < NSLAB; s++) {
            if (s + 1 < NSLAB) asm volatile("cp.async.wait_group 1;\n");
            else               asm volatile("cp.async.wait_group 0;\n");
            __syncthreads();
            compute(s & 1);
            __syncthreads();
            if (s + 2 < NSLAB) issue(s + 2, s & 1);
        }

        // ---- epilogue ----
        if (kind == 0) {
#pragma unroll
            for (int mi = 0; mi < 4; mi++) {
#pragma unroll
                for (int ni = 0; ni < 4; ni++) {
                    int m0 = bm + wm * 64 + mi * 16 + q;
                    int n0 = bn + wn * 32 + ni * 8 + r * 2;
                    float* a = acc[mi][ni];
                    float bv0 = fc0b[n0], bv1 = fc0b[n0 + 1];
                    float v00 = a[0] + bv0, v01 = a[1] + bv1;
                    float v10 = a[2] + bv0, v11 = a[3] + bv1;
                    bf16 h0, l0, h1, l1;
                    split1(v00, h0, l0); split1(v01, h1, l1);
                    *(__nv_bfloat162*)(xhi + (size_t)m0 * HH + n0) = __nv_bfloat162(h0, h1);
                    *(__nv_bfloat162*)(xlo + (size_t)m0 * HH + n0) = __nv_bfloat162(l0, l1);
                    split1(v10, h0, l0); split1(v11, h1, l1);
                    *(__nv_bfloat162*)(xhi + (size_t)(m0 + 8) * HH + n0) = __nv_bfloat162(h0, h1);
                    *(__nv_bfloat162*)(xlo + (size_t)(m0 + 8) * HH + n0) = __nv_bfloat162(l0, l1);
                }
            }
            __threadfence();
            __syncthreads();
            if (tid == 0) {
                if (atomicAdd(&done[400 + fcb], 1) == 5) {
                    if (atomicSub(&dep[fcb], 1) == 1) {
                        int p = atomicAdd(&sched[1241], 1);
                        __stcg(&rq[p], fcb);
                    }
                }
            }
        } else if (kind == 2) {
            // fc1 partial: part[t] += nothing (exclusive), raw store
            float* dst0 = part + ((size_t)t * BB);
#pragma unroll
            for (int mi = 0; mi < 4; mi++) {
#pragma unroll
                for (int ni = 0; ni < 4; ni++) {
                    int m0 = bm + wm * 64 + mi * 16 + q;
                    int n0 = bn + wn * 32 + ni * 8 + r * 2;
                    float* a = acc[mi][ni];
                    float* dst = part + ((size_t)t * BB + m0) * HH + n0;
                    dst[0] = a[0]; dst[1] = a[1];
                    dst += (size_t)8 * HH;
                    dst[0] = a[2]; dst[1] = a[3];
                }
            }
            (void)dst0;
        } else {
            const float* bias = bcomb + (size_t)l * G4H;
            float* cst = call + (size_t)l * BB * HH;
            bf16* Chi = xhi + ((size_t)(l + 1) * WW + t) * BB * HH;
            bf16* Clo = xlo + ((size_t)(l + 1) * WW + t) * BB * HH;
#pragma unroll
            for (int mi = 0; mi < 4; mi++) {
#pragma unroll
                for (int ni = 0; ni < 4; ni++) {
                    int m0 = bm + wm * 64 + mi * 16 + q;
                    int n0 = bn + wn * 32 + ni * 8 + r * 2;
                    float* a = acc[mi][ni];
                    float bv0 = bias[n0], bv1 = bias[n0 + 1];
                    float a0 = a[0] + bv0, a1 = a[1] + bv1;
                    float a2 = a[2] + bv0, a3 = a[3] + bv1;
                    float p0 = __shfl_xor_sync(0xFFFFFFFFu, a0, 1);
                    float p1 = __shfl_xor_sync(0xFFFFFFFFu, a1, 1);
                    float p2 = __shfl_xor_sync(0xFFFFFFFFu, a2, 1);
                    float p3 = __shfl_xor_sync(0xFFFFFFFFu, a3, 1);
                    if ((r & 1) == 0) {
                        int n = n0 >> 2;
#pragma unroll
                        for (int rr = 0; rr < 2; rr++) {
                            int m = m0 + rr * 8;
                            float gi = rr ? a2 : a0;
                            float gf = rr ? a3 : a1;
                            float gg = rr ? p2 : p0;
                            float go = rr ? p3 : p1;
                            float cn;
                            if (t == 0) {
                                cn = sigm(gi) * tanhf(gg);
                            } else {
                                float cold = __ldcg(cst + (size_t)m * HH + n);
                                cn = sigm(gf) * cold + sigm(gi) * tanhf(gg);
                            }
                            __stcg(cst + (size_t)m * HH + n, cn);
                            float h = sigm(go) * tanhf(cn);
                            bf16 hh, hl;
                            split1(h, hh, hl);
                            Chi[(size_t)m * HH + n] = hh;
                            Clo[(size_t)m * HH + n] = hl;
                        }
                    }
                }
            }
            __threadfence();
            __syncthreads();
            if (tid == 0) {
                int batch = fcb;
                if (atomicAdd(&done[batch], 1) == TPB - 1) {
                    if (l < LAYERS - 1) {
                        if (atomicSub(&dep[batch + 40], 1) == 1) {
                            int p = atomicAdd(&sched[1241], 1);
                            __stcg(&rq[p], batch + 40);
                        }
                    } else {
                        __stcg(&fc1rdy[t * 4 + ch], 1);     // release fc1 (t,ch)
                    }
                    if (t < WW - 1) {
                        if (atomicSub(&dep[batch + 4], 1) == 1) {
                            int p = atomicAdd(&sched[1241], 1);
                            __stcg(&rq[p], batch + 4);
                        }
                    }
                }
            }
        }
    }
}

// ---------------- prep (merged): weights + bias + sched init + input transpose
__global__ void prep_all(const float* __restrict__ fc0_w, const float* __restrict__ fc1_w,
                         const float* __restrict__ wih, const float* __restrict__ whh,
                         const float* __restrict__ bih, const float* __restrict__ bhh,
                         const float* __restrict__ xpos,
                         bf16* __restrict__ f0h, bf16* __restrict__ f0l,
                         bf16* __restrict__ f1h, bf16* __restrict__ f1l,
                         bf16* __restrict__ ihh, bf16* __restrict__ ihl,
                         bf16* __restrict__ hhh, bf16* __restrict__ hhl,
                         float* __restrict__ bc,
                         bf16* __restrict__ xch, bf16* __restrict__ xcl,
                         int* __restrict__ sched)
{
    int i = blockIdx.x * blockDim.x + threadIdx.x;
    const int NA = HH * HH;
    const int NB = NA + HH * KFC1;
    const int NP = 2 * LAYERS * G4H * HH;
    if (i < NA) { split1(fc0_w[i], f0h[i], f0l[i]); return; }
    if (i < NB) { int j = i - NA; split1(fc1_w[j], f1h[j], f1l[j]); return; }
    int i2 = i - NB;
    if (i2 < NP) {
        int sel = i2 >= NP / 2;
        int ii = sel ? i2 - NP / 2 : i2;
        int k = ii % HH;
        int j = (ii / HH) % G4H;
        int l = ii / (HH * G4H);
        int n = j >> 2, g = j & 3;
        const float* src = sel ? whh : wih;
        float v = src[(size_t)l * G4H * HH + (size_t)(g * HH + n) * HH + k];
        if (sel) split1(v, hhh[ii], hhl[ii]);
        else     split1(v, ihh[ii], ihl[ii]);
        return;
    }
    int i3 = i2 - NP;
    if (i3 < LAYERS * G4H) {
        int j = i3 % G4H;
        int l = i3 / G4H;
        int n = j >> 2, g = j & 3;
        bc[i3] = bih[l * G4H + g * HH + n] + bhh[l * G4H + g * HH + n];
        return;
    }
    int i4 = i3 - LAYERS * G4H;
    if (i4 < 1344) {
        if (i4 < 440) sched[i4] = 0;                       // done
        else if (i4 < 840) {                               // dep[400]
            int b = i4 - 440;
            int tt = (b % 40) >> 2;
            sched[i4] = 1 + (tt > 0 ? 1 : 0);
        } else if (i4 < 1240) sched[i4] = -1;              // readyq
        else sched[i4] = 0;                                // ticket, qtail, fc1rdy
        return;
    }
    int i5 = i4 - 1344;
    if (i5 < TB * HH) {
        // (B,W,H) fp32 -> (W*B, H) split bf16
        int k = i5 % HH;
        int row = i5 / HH;
        int t = row / BB, b = row % BB;
        split1(xpos[((size_t)b * WW + t) * HH + k], xch[i5], xcl[i5]);
    }
}

__global__ void reduce_fc1(const float* __restrict__ part, const float* __restrict__ b,
                           float* __restrict__ out)
{
    int i = blockIdx.x * blockDim.x + threadIdx.x;
    if (i >= BB * HH) return;
    int m = i / HH, n = i % HH;
    float s = b[n];
#pragma unroll
    for (int t = 0; t < WW; t++) s += part[((size_t)t * BB + m) * HH + n];
    out[i] = s;
}

// ---------------- host -------------------------------------------------------
extern "C" void kernel_launch(void* const* d_in, const int* in_sizes, int n_in,
                              void* d_out, int out_size)
{
    const float* xpos  = (const float*)d_in[0];
    const float* fc0_w = (const float*)d_in[1];
    const float* fc0_b = (const float*)d_in[2];
    const float* w_ih  = (const float*)d_in[3];
    const float* w_hh  = (const float*)d_in[4];
    const float* b_ih  = (const float*)d_in[5];
    const float* b_hh  = (const float*)d_in[6];
    const float* fc1_w = (const float*)d_in[7];
    const float* fc1_b = (const float*)d_in[8];
    float* out = (float*)d_out;

    bf16 *xhi, *xlo, *xcathi, *xcatlo;
    bf16 *fc0whi, *fc0wlo, *fc1whi, *fc1wlo, *wihhi, *wihlo, *whhhi, *whhlo;
    float *c, *bcomb, *part;
    int* sched;
    cudaGetSymbolAddress((void**)&xhi,   g_xhi);
    cudaGetSymbolAddress((void**)&xlo,   g_xlo);
    cudaGetSymbolAddress((void**)&xcathi, g_xcathi);
    cudaGetSymbolAddress((void**)&xcatlo, g_xcatlo);
    cudaGetSymbolAddress((void**)&fc0whi, g_fc0whi);
    cudaGetSymbolAddress((void**)&fc0wlo, g_fc0wlo);
    cudaGetSymbolAddress((void**)&fc1whi, g_fc1whi);
    cudaGetSymbolAddress((void**)&fc1wlo, g_fc1wlo);
    cudaGetSymbolAddress((void**)&wihhi, g_wihhi);
    cudaGetSymbolAddress((void**)&wihlo, g_wihlo);
    cudaGetSymbolAddress((void**)&whhhi, g_whhhi);
    cudaGetSymbolAddress((void**)&whhlo, g_whhlo);
    cudaGetSymbolAddress((void**)&c,     g_c);
    cudaGetSymbolAddress((void**)&bcomb, g_bcomb);
    cudaGetSymbolAddress((void**)&part,  g_part);
    cudaGetSymbolAddress((void**)&sched, g_sched);

    static bool once = false;
    if (!once) {
        cudaFuncSetAttribute(mega_kernel, cudaFuncAttributeMaxDynamicSharedMemorySize, SMEM_BYTES);
        once = true;
    }

    const int EL = 256;

    // launch 0: merged prep (weights, biases, scheduler init, input transpose)
    {
        int n = HH * HH + HH * KFC1 + 2 * LAYERS * G4H * HH + LAYERS * G4H + 1344
              + TB * HH;
        prep_all<<<(n + EL - 1) / EL, EL>>>(fc0_w, fc1_w, w_ih, w_hh, b_ih, b_hh, xpos,
                                            fc0whi, fc0wlo, fc1whi, fc1wlo,
                                            wihhi, wihlo, whhhi, whhlo, bcomb,
                                            xcathi, xcatlo, sched);
    }

    // launch 1: dataflow mega kernel (fc0 + all layers/steps + fc1 partials)
    mega_kernel<<<LGRID, 256, SMEM_BYTES>>>(
        xhi, xlo, xcathi, xcatlo, fc0whi, fc0wlo, fc0_b, fc1whi, fc1wlo,
        wihhi, wihlo, whhhi, whhlo, bcomb, c, part, sched);

    // launch 2: fc1 reduce (+bias)
    reduce_fc1<<<(BB * HH + EL - 1) / EL, EL>>>(part, fc1_b, out);
}